// round 16
// baseline (speedup 1.0000x reference)
#include <cuda_runtime.h>
#include <cuda_bf16.h>
#include <cstdint>

#define BATCH   64
#define CDIM    64
#define WDIM    16384
#define SPLITS  4
#define KSP     (WDIM / SPLITS)      // 4096 fp32 cols per CTA
#define KTF     64                   // fp32 cols per chunk (half-chunk pipeline)
#define NCH     (KSP / KTF)          // 64 chunks
#define TGRID   256                  // tail grid (64 batches x 4 quarters)

// Scratch (static device arrays; no allocation)
__device__ float g_part[BATCH * SPLITS * 4096];   // 4 MB
__device__ float g_mat [BATCH * 4096];            // 1 MB
__device__ float d_mat [BATCH * BATCH];
__device__ float g_Snp [BATCH * 4];               // per-quarter Sn partials
__device__ int   g_cnt1, g_cnt2;
__device__ volatile int g_flag1;

__device__ __forceinline__ unsigned cvta_s(const void* p) {
    return (unsigned)__cvta_generic_to_shared(p);
}

__device__ __forceinline__ void ldsm_x4(unsigned addr, unsigned &r0, unsigned &r1,
                                        unsigned &r2, unsigned &r3) {
    asm volatile("ldmatrix.sync.aligned.m8n8.x4.shared.b16 {%0,%1,%2,%3}, [%4];\n"
                 : "=r"(r0), "=r"(r1), "=r"(r2), "=r"(r3) : "r"(addr));
}

__device__ __forceinline__ void mma_bf16(float* c, unsigned a0, unsigned a1,
                                         unsigned a2, unsigned a3,
                                         unsigned b0, unsigned b1) {
    asm volatile(
        "mma.sync.aligned.m16n8k16.row.col.f32.bf16.bf16.f32 "
        "{%0,%1,%2,%3}, {%4,%5,%6,%7}, {%8,%9}, {%0,%1,%2,%3};\n"
        : "+f"(c[0]), "+f"(c[1]), "+f"(c[2]), "+f"(c[3])
        : "r"(a0), "r"(a1), "r"(a2), "r"(a3), "r"(b0), "r"(b1));
}

// ---------------------------------------------------------------------------
// Kernel 1: partial Grams. grid = 256 (batch x split), 256 threads, occ 2.
// CTA (b, s): G_part[b][s] = X[b][:, sK:(s+1)K] * X^T  (64x64 fp32 acc).
// Half-chunk (64 fp32 cols = 128B bf16/row) double-buffered smem ring with
// register ping-pong (A/B): LDG for chunk c+2 is issued two MMA phases before
// its STS consumes it, fully covering DRAM latency.
// smem: 2 stages x 64 rows x 128B; 16B unit u stored at u^(row&7) (XOR-8).
// 8 warps: 2x2 spatial tiles (32x32) x 2 k-groups (2 of 4 k16-steps each).
// ---------------------------------------------------------------------------
__global__ __launch_bounds__(256, 2) void gram_kernel(const float* __restrict__ inp) {
    __shared__ __align__(1024) __nv_bfloat16 tile[2][64 * 64];   // 2 x 8 KB

    const int tid = threadIdx.x, wid = tid >> 5, lane = tid & 31;
    const int bid = blockIdx.x, b = bid >> 2, s = bid & 3;

    if (bid == 0 && tid == 0) { g_cnt1 = 0; g_cnt2 = 0; g_flag1 = 0; }

    // ---- loader mapping: row = tid>>2 (0..63), q = tid&3; 4 float4/chunk
    const int row = tid >> 2, q = tid & 3, rx = row & 7;
    const float4* src4 = reinterpret_cast<const float4*>(
        inp + (size_t)(b * CDIM + row) * WDIM + s * KSP);
    const unsigned stbase = cvta_s(&tile[0][0]);
    const unsigned sts0 = (unsigned)(row * 128 + (((2 * q)     ^ rx) << 4));
    const unsigned sts1 = (unsigned)(row * 128 + (((2 * q + 1) ^ rx) << 4));

    // ---- MMA mapping
    const int tlid = wid & 3;                 // spatial tile
    const int tm = (tlid & 1) * 32, tn = (tlid >> 1) * 32;
    const int kg = wid >> 2;                  // k-group (ksteps kg*2 .. kg*2+1)

    const int arow0 = tm + (lane & 7) + 8 * ((lane >> 3) & 1);
    const int ac    = lane >> 4;
    const int brow0 = tn + (lane & 7) + 8 * (lane >> 4);
    const int bc    = (lane >> 3) & 1;
    const unsigned aBase0 = (unsigned)(arow0 * 128),        aX0 = (unsigned)(arow0 & 7);
    const unsigned aBase1 = (unsigned)((arow0 + 16) * 128), aX1 = (unsigned)((arow0 + 16) & 7);
    const unsigned bBase0 = (unsigned)(brow0 * 128),        bX0 = (unsigned)(brow0 & 7);
    const unsigned bBase1 = (unsigned)((brow0 + 16) * 128), bX1 = (unsigned)((brow0 + 16) & 7);

    float acc[2][4][4];
#pragma unroll
    for (int mi = 0; mi < 2; ++mi)
#pragma unroll
        for (int ni = 0; ni < 4; ++ni)
#pragma unroll
            for (int r = 0; r < 4; ++r) acc[mi][ni][r] = 0.0f;

    auto sts_buf = [&](const float4* buf, unsigned sb) {
        __nv_bfloat162 p0 = __floats2bfloat162_rn(buf[0].x, buf[0].y);
        __nv_bfloat162 p1 = __floats2bfloat162_rn(buf[0].z, buf[0].w);
        __nv_bfloat162 p2 = __floats2bfloat162_rn(buf[1].x, buf[1].y);
        __nv_bfloat162 p3 = __floats2bfloat162_rn(buf[1].z, buf[1].w);
        asm volatile("st.shared.v4.b32 [%0], {%1,%2,%3,%4};"
            :: "r"(sb + sts0),
               "r"(*(unsigned*)&p0), "r"(*(unsigned*)&p1),
               "r"(*(unsigned*)&p2), "r"(*(unsigned*)&p3) : "memory");
        p0 = __floats2bfloat162_rn(buf[2].x, buf[2].y);
        p1 = __floats2bfloat162_rn(buf[2].z, buf[2].w);
        p2 = __floats2bfloat162_rn(buf[3].x, buf[3].y);
        p3 = __floats2bfloat162_rn(buf[3].z, buf[3].w);
        asm volatile("st.shared.v4.b32 [%0], {%1,%2,%3,%4};"
            :: "r"(sb + sts1),
               "r"(*(unsigned*)&p0), "r"(*(unsigned*)&p1),
               "r"(*(unsigned*)&p2), "r"(*(unsigned*)&p3) : "memory");
    };

    auto mma_stage = [&](unsigned sb) {
#pragma unroll
        for (int u = 0; u < 2; ++u) {
            const int kk = kg * 2 + u;
            const unsigned ca = (unsigned)(2 * kk + ac);
            const unsigned cb = (unsigned)(2 * kk + bc);
            unsigned a0, a1, a2, a3, a4, a5, a6, a7;
            unsigned b0, b1, b2, b3, b4, b5, b6, b7;
            ldsm_x4(sb + aBase0 + ((ca ^ aX0) << 4), a0, a1, a2, a3);
            ldsm_x4(sb + aBase1 + ((ca ^ aX1) << 4), a4, a5, a6, a7);
            ldsm_x4(sb + bBase0 + ((cb ^ bX0) << 4), b0, b1, b2, b3);
            ldsm_x4(sb + bBase1 + ((cb ^ bX1) << 4), b4, b5, b6, b7);
            mma_bf16(acc[0][0], a0, a1, a2, a3, b0, b1);
            mma_bf16(acc[0][1], a0, a1, a2, a3, b2, b3);
            mma_bf16(acc[0][2], a0, a1, a2, a3, b4, b5);
            mma_bf16(acc[0][3], a0, a1, a2, a3, b6, b7);
            mma_bf16(acc[1][0], a4, a5, a6, a7, b0, b1);
            mma_bf16(acc[1][1], a4, a5, a6, a7, b2, b3);
            mma_bf16(acc[1][2], a4, a5, a6, a7, b4, b5);
            mma_bf16(acc[1][3], a4, a5, a6, a7, b6, b7);
        }
    };

    float4 bufA[4], bufB[4];
#pragma unroll
    for (int j = 0; j < 4; ++j) bufA[j] = src4[4 * q + j];           // chunk 0
#pragma unroll
    for (int j = 0; j < 4; ++j) bufB[j] = src4[16 + 4 * q + j];      // chunk 1

    for (int c = 0; c < NCH; c += 2) {
        // even half-chunk -> stage 0, buffer A
        sts_buf(bufA, stbase);
        __syncthreads();
        if (c + 2 < NCH) {
            const float4* p = src4 + (c + 2) * 16 + 4 * q;
#pragma unroll
            for (int j = 0; j < 4; ++j) bufA[j] = p[j];
        }
        mma_stage(stbase);
        // odd half-chunk -> stage 1, buffer B
        sts_buf(bufB, stbase + 8192u);
        __syncthreads();
        if (c + 3 < NCH) {
            const float4* p = src4 + (c + 3) * 16 + 4 * q;
#pragma unroll
            for (int j = 0; j < 4; ++j) bufB[j] = p[j];
        }
        mma_stage(stbase + 8192u);
    }

    // ---- epilogue: combine the two k-group partials via smem, write g_part
    __syncthreads();
    float* stg = reinterpret_cast<float*>(&tile[0][0]);   // 16 KB staging
    const int crow = lane >> 2, ccol2 = (lane & 3) * 2;
    if (kg == 1) {
#pragma unroll
        for (int mi = 0; mi < 2; ++mi)
#pragma unroll
            for (int ni = 0; ni < 4; ++ni) {
                float* p = stg + tlid * 1024 + (mi * 16 + crow) * 32 + ni * 8 + ccol2;
                p[0] = acc[mi][ni][0]; p[1] = acc[mi][ni][1];
                p[8 * 32] = acc[mi][ni][2]; p[8 * 32 + 1] = acc[mi][ni][3];
            }
    }
    __syncthreads();
    if (kg == 0) {
        float* gp = g_part + (size_t)(b * SPLITS + s) * 4096;
#pragma unroll
        for (int mi = 0; mi < 2; ++mi)
#pragma unroll
            for (int ni = 0; ni < 4; ++ni) {
                const float* p = stg + tlid * 1024 + (mi * 16 + crow) * 32 + ni * 8 + ccol2;
                const int gr = tm + mi * 16 + crow, gc = tn + ni * 8 + ccol2;
                *reinterpret_cast<float2*>(gp + gr * 64 + gc) =
                    make_float2(acc[mi][ni][0] + p[0], acc[mi][ni][1] + p[1]);
                *reinterpret_cast<float2*>(gp + (gr + 8) * 64 + gc) =
                    make_float2(acc[mi][ni][2] + p[8 * 32], acc[mi][ni][3] + p[8 * 32 + 1]);
            }
    }
}

// ---------------------------------------------------------------------------
// Kernel 2: fused tail. grid = 256 CTAs (all resident at occ 2), 256 threads.
// CTA (i = bid>>2, qd = bid&3):
//   P1: fold quarter qd of batch i -> g_mat
//   grid-barrier (atomic arrive + flag release; pollers use plain L2 loads)
//   P2: load full g_mat[i] to smem; compute D[i][j] for 16 j's (8 warps x 2 j,
//       interleaved for MLP); per-quarter Sn partial -> g_Snp (deterministic)
//   ticket barrier; last CTA computes the scalar loss.
// Target dtype detected at runtime (JAX x64-off demotes int64 -> int32).
// ---------------------------------------------------------------------------
__global__ __launch_bounds__(256, 2) void tail_kernel(const void* __restrict__ tgt_raw,
                                                      float* __restrict__ out) {
    __shared__ __align__(16) float gi[4096];
    __shared__ float Sns[64];
    __shared__ int   Tg[64];
    __shared__ int   is64s;
    __shared__ int   lastf;
    __shared__ float wsn[8];
    __shared__ float red[256];
    __shared__ int   redc[256];

    const int tid = threadIdx.x, wid = tid >> 5, lane = tid & 31;
    const int i = blockIdx.x >> 2, qd = blockIdx.x & 3;
    const float inv = 1.0f / ((float)CDIM * (float)WDIM);

    if (tid == 0) {
        const int* t32 = (const int*)tgt_raw;
        int f = 0;
#pragma unroll
        for (int k = 1; k < 64; k += 2) f |= t32[k];
        is64s = (f == 0) ? 1 : 0;
    }
    __syncthreads();
    if (tid < 64)
        Tg[tid] = is64s ? (int)((const long long*)tgt_raw)[tid] : ((const int*)tgt_raw)[tid];

    // ---- P1: fold quarter qd of batch i (256 float4 / 256 threads)
    {
        const float4* b0 = reinterpret_cast<const float4*>(
            g_part + (size_t)i * SPLITS * 4096 + qd * 1024) + tid;
        const float4* b1 = b0 + 1024;   // +4096 floats
        const float4* b2 = b1 + 1024;
        const float4* b3 = b2 + 1024;
        float4 v0 = *b0, v1 = *b1, v2 = *b2, v3 = *b3;
        float4 r;
        r.x = ((v0.x + v1.x) + (v2.x + v3.x)) * inv;
        r.y = ((v0.y + v1.y) + (v2.y + v3.y)) * inv;
        r.z = ((v0.z + v1.z) + (v2.z + v3.z)) * inv;
        r.w = ((v0.w + v1.w) + (v2.w + v3.w)) * inv;
        reinterpret_cast<float4*>(g_mat + (size_t)i * 4096 + qd * 1024)[tid] = r;
    }
    __threadfence();
    __syncthreads();
    if (tid == 0) {
        int t = atomicAdd(&g_cnt1, 1);
        if (t == TGRID - 1) {
            g_flag1 = 1;                       // release (volatile store, L2)
        } else {
            while (g_flag1 == 0) { __nanosleep(64); }
        }
    }
    __syncthreads();
    __threadfence();

    // ---- P2: load gi, compute 16 distances (2 j's per warp, interleaved)
    {
        const float4* gsrc = reinterpret_cast<const float4*>(g_mat + (size_t)i * 4096);
        float4* gi4 = reinterpret_cast<float4*>(gi);
        for (int t = tid; t < 1024; t += 256) gi4[t] = gsrc[t];
    }
    __syncthreads();

    const int j0 = qd * 16 + wid * 2;
    const int j1 = j0 + 1;
    {
        const float4* gj0 = reinterpret_cast<const float4*>(g_mat + (size_t)j0 * 4096);
        const float4* gj1 = reinterpret_cast<const float4*>(g_mat + (size_t)j1 * 4096);
        const float4* gi4 = reinterpret_cast<const float4*>(gi);
        float s0 = 0.0f, s1 = 0.0f;
#pragma unroll 4
        for (int cq = lane; cq < 1024; cq += 32) {
            const float4 a  = gi4[cq];
            const float4 p  = gj0[cq];
            const float4 r  = gj1[cq];
            float e;
            e = a.x - p.x; s0 = fmaf(e, e, s0);
            e = a.y - p.y; s0 = fmaf(e, e, s0);
            e = a.z - p.z; s0 = fmaf(e, e, s0);
            e = a.w - p.w; s0 = fmaf(e, e, s0);
            e = a.x - r.x; s1 = fmaf(e, e, s1);
            e = a.y - r.y; s1 = fmaf(e, e, s1);
            e = a.z - r.z; s1 = fmaf(e, e, s1);
            e = a.w - r.w; s1 = fmaf(e, e, s1);
        }
#pragma unroll
        for (int o = 16; o > 0; o >>= 1) {
            s0 += __shfl_xor_sync(0xffffffffu, s0, o);
            s1 += __shfl_xor_sync(0xffffffffu, s1, o);
        }
        if (lane == 0) {
            const float d0 = s0 * (1.0f / 4096.0f);
            const float d1 = s1 * (1.0f / 4096.0f);
            d_mat[i * 64 + j0] = d0;
            d_mat[i * 64 + j1] = d1;
            const int ti = Tg[i];
            float sn = 0.0f;
            if (Tg[j0] != ti) sn += expf(1.0f - d0);
            if (Tg[j1] != ti) sn += expf(1.0f - d1);
            wsn[wid] = sn;
        }
    }
    __syncthreads();
    if (tid == 0) {
        float sn = 0.0f;
#pragma unroll
        for (int w = 0; w < 8; ++w) sn += wsn[w];
        g_Snp[i * 4 + qd] = sn;
    }
    __threadfence();
    __syncthreads();
    if (tid == 0) lastf = (atomicAdd(&g_cnt2, 1) == TGRID - 1) ? 1 : 0;
    __syncthreads();
    if (!lastf) return;
    __threadfence();

    // ---- P3: final loss in the last-arriving CTA (reuse gi as D)
    for (int t = tid; t < 4096; t += 256) gi[t] = d_mat[t];
    if (tid < 64) {
        const float* sp = g_Snp + tid * 4;
        Sns[tid] = (sp[0] + sp[1]) + (sp[2] + sp[3]);
    }
    __syncthreads();

    float acc = 0.0f;
    int cnt = 0;
    for (int p = tid; p < 4096; p += 256) {
        const int ii = p >> 6, jj = p & 63;
        if (jj > ii && Tg[ii] == Tg[jj]) {
            float Jv = logf(Sns[ii] + Sns[jj]) + gi[p];
            Jv = fmaxf(Jv, 0.0f);
            acc = fmaf(Jv, Jv, acc);
            cnt++;
        }
    }
    red[tid] = acc;
    redc[tid] = cnt;
    __syncthreads();
    for (int o = 128; o > 0; o >>= 1) {
        if (tid < o) { red[tid] += red[tid + o]; redc[tid] += redc[tid + o]; }
        __syncthreads();
    }
    if (tid == 0) out[0] = red[0] / (2.0f * (float)redc[0]);
}

// ---------------------------------------------------------------------------
extern "C" void kernel_launch(void* const* d_in, const int* in_sizes, int n_in,
                              void* d_out, int out_size) {
    const float* inp = (const float*)d_in[0];
    const void*  tgt = (const void*)d_in[1];
    float*       out = (float*)d_out;

    gram_kernel<<<BATCH * SPLITS, 256>>>(inp);
    tail_kernel<<<TGRID, 256>>>(tgt, out);
}